// round 3
// baseline (speedup 1.0000x reference)
#include <cuda_runtime.h>

// Fused 2-layer LSTM + MLP, persistent pipelined kernel, round 3.
// Grid 128 x 384. CTA owns 4 batch rows, 1000 steps.
// L1 group (256 thr): thread = (unit i in 0..63, k-quarter kq). Owns all 4
//   gates of unit i for batch beta(kq) after a 6-shfl butterfly; applies the
//   LSTM update locally. No intra-step barriers, no gate SMEM staging.
// L2 group (128 thr): same scheme, 32 units, runs one step behind (skewed).
// Weights pre-packed as f32x2 doubles (gate pairs) in registers; SMEM
// activations stored duplicated [v,v] so LDS.128 feeds fma.rn.f32x2 directly.
// Both activation arrays double-buffered -> single __syncthreads per step.

#define T_STEPS 1000

__device__ __forceinline__ float sigf(float x) {
    float e = exp2f(-1.4426950408889634f * x);
    return __fdividef(1.0f, 1.0f + e);
}
__device__ __forceinline__ float tanh_fast(float x) {
    x = fminf(16.0f, fmaxf(-16.0f, x));
    float e = exp2f(-2.8853900817779268f * x);   // exp(-2x)
    return __fdividef(1.0f - e, 1.0f + e);
}
__device__ __forceinline__ double pk2(float lo, float hi) {
    double r; asm("mov.b64 %0, {%1,%2};" : "=d"(r) : "f"(lo), "f"(hi)); return r;
}
__device__ __forceinline__ void upk2(double v, float &lo, float &hi) {
    asm("mov.b64 {%0,%1}, %2;" : "=f"(lo), "=f"(hi) : "d"(v));
}
__device__ __forceinline__ void fma2(double &acc, double a, double b) {
    asm("fma.rn.f32x2 %0, %1, %2, %0;" : "+d"(acc) : "d"(a), "d"(b));
}
__device__ __forceinline__ double add2(double a, double b) {
    double r; asm("add.rn.f32x2 %0, %1, %2;" : "=d"(r) : "d"(a), "d"(b)); return r;
}

__global__ void __launch_bounds__(384, 1)
audio_lstm_kernel(const float* __restrict__ x,
                  const float* __restrict__ w_ih1, const float* __restrict__ w_hh1,
                  const float* __restrict__ b_ih1, const float* __restrict__ b_hh1,
                  const float* __restrict__ w_ih2, const float* __restrict__ w_hh2,
                  const float* __restrict__ b_ih2, const float* __restrict__ b_hh2,
                  const float* __restrict__ w_fc1, const float* __restrict__ b_fc1,
                  const float* __restrict__ w_fc2, const float* __restrict__ b_fc2,
                  float* __restrict__ out)
{
    // Duplicated layout: row r holds [v0,v0,v1,v1,v2,v2,v3,v3] (b = batch).
    // v1d rows: 0-25 x_t, 26-89 h1, 90-91 zero pad. Double buffered.
    __shared__ __align__(16) float v1d[2][92][8];
    // v2d rows: 0-63 h1 (for L2), 64-95 h2. Double buffered.
    __shared__ __align__(16) float v2d[2][96][8];
    __shared__ float sf[4][16];

    const int tid = threadIdx.x;
    const int bbase = blockIdx.x * 4;
    const bool isL1 = tid < 256;

    // Role-shared registers
    double wp0[24], wp1[24];          // packed (i,f) and (g,o) weight pairs
    float bi, bf, bg, bo;
    int unit, kq;
    float c = 0.0f;

    if (isL1) {
        unit = tid >> 2; kq = tid & 3;
#pragma unroll
        for (int kk = 0; kk < 23; kk++) {
            int k = 4 * kk + kq;
            float wi = 0.f, wf = 0.f, wg = 0.f, wo = 0.f;
            if (k < 26) {
                wi = w_ih1[unit * 26 + k];
                wf = w_ih1[(64 + unit) * 26 + k];
                wg = w_ih1[(128 + unit) * 26 + k];
                wo = w_ih1[(192 + unit) * 26 + k];
            } else if (k < 90) {
                int km = k - 26;
                wi = w_hh1[unit * 64 + km];
                wf = w_hh1[(64 + unit) * 64 + km];
                wg = w_hh1[(128 + unit) * 64 + km];
                wo = w_hh1[(192 + unit) * 64 + km];
            }
            wp0[kk] = pk2(wi, wf);
            wp1[kk] = pk2(wg, wo);
        }
        bi = b_ih1[unit] + b_hh1[unit];
        bf = b_ih1[64 + unit] + b_hh1[64 + unit];
        bg = b_ih1[128 + unit] + b_hh1[128 + unit];
        bo = b_ih1[192 + unit] + b_hh1[192 + unit];
    } else {
        const int u = tid - 256;
        unit = u >> 2; kq = u & 3;
#pragma unroll
        for (int kk = 0; kk < 24; kk++) {
            int k = 4 * kk + kq;      // < 96 always
            float wi, wf, wg, wo;
            if (k < 64) {
                wi = w_ih2[unit * 64 + k];
                wf = w_ih2[(32 + unit) * 64 + k];
                wg = w_ih2[(64 + unit) * 64 + k];
                wo = w_ih2[(96 + unit) * 64 + k];
            } else {
                int km = k - 64;
                wi = w_hh2[unit * 32 + km];
                wf = w_hh2[(32 + unit) * 32 + km];
                wg = w_hh2[(64 + unit) * 32 + km];
                wo = w_hh2[(96 + unit) * 32 + km];
            }
            wp0[kk] = pk2(wi, wf);
            wp1[kk] = pk2(wg, wo);
        }
        bi = b_ih2[unit] + b_hh2[unit];
        bf = b_ih2[32 + unit] + b_hh2[32 + unit];
        bg = b_ih2[64 + unit] + b_hh2[64 + unit];
        bo = b_ih2[96 + unit] + b_hh2[96 + unit];
    }
    // batch owned after butterfly: kq 0,1,2,3 -> 0,2,1,3
    const int beta = ((kq & 1) << 1) | (kq >> 1);
    const bool hi1 = kq & 1;
    const bool hi2 = kq & 2;

    // Zero both buffers of both arrays
    for (int idx = tid; idx < 2 * 92 * 8; idx += 384) ((float*)v1d)[idx] = 0.0f;
    for (int idx = tid; idx < 2 * 96 * 8; idx += 384) ((float*)v2d)[idx] = 0.0f;

    // x layout: x[b][i][t]
    const int xi = tid % 26;
    const int xb = tid / 26;
    const float* xptr = x + (size_t)(bbase + xb) * 26 * T_STEPS + (size_t)xi * T_STEPS;
    __syncthreads();
    if (tid < 104) {
        float x0 = xptr[0];
        *(double*)&v1d[0][xi][2 * xb] = pk2(x0, x0);
    }
    __syncthreads();

    // iter n: L1 computes step n (reads v1d[cur], writes v1d[nxt], v2d[cur]);
    //         L2 computes step n-1 (reads v2d[nxt], writes v2d[cur] rows 64+).
    for (int n = 0; n <= T_STEPS; n++) {
        const int cur = n & 1, nxt = cur ^ 1;
        if (isL1) {
            if (n < T_STEPS) {
                const bool xact = (tid < 104) && (n + 1 < T_STEPS);
                float xr = 0.0f;
                if (xact) xr = xptr[n + 1];

                double a00 = 0, a01 = 0, a02 = 0, a03 = 0;
                double a10 = 0, a11 = 0, a12 = 0, a13 = 0;
                const float* base = &v1d[cur][0][0] + 8 * kq;
#pragma unroll
                for (int kk = 0; kk < 23; kk++) {
                    const float* r = base + 32 * kk;
                    double2 vA = *(const double2*)r;        // (v0,v0),(v1,v1)
                    double2 vB = *(const double2*)(r + 4);  // (v2,v2),(v3,v3)
                    fma2(a00, wp0[kk], vA.x); fma2(a01, wp0[kk], vA.y);
                    fma2(a02, wp0[kk], vB.x); fma2(a03, wp0[kk], vB.y);
                    fma2(a10, wp1[kk], vA.x); fma2(a11, wp1[kk], vA.y);
                    fma2(a12, wp1[kk], vB.x); fma2(a13, wp1[kk], vB.y);
                }
                // butterfly round 1 (xor 1): keep batches {0,1} or {2,3}
                double t0 = hi1 ? a00 : a02;
                double t1 = hi1 ? a01 : a03;
                double t2 = hi1 ? a10 : a12;
                double t3 = hi1 ? a11 : a13;
                t0 = __shfl_xor_sync(0xffffffffu, t0, 1);
                t1 = __shfl_xor_sync(0xffffffffu, t1, 1);
                t2 = __shfl_xor_sync(0xffffffffu, t2, 1);
                t3 = __shfl_xor_sync(0xffffffffu, t3, 1);
                double k00 = add2(hi1 ? a02 : a00, t0);
                double k01 = add2(hi1 ? a03 : a01, t1);
                double k10 = add2(hi1 ? a12 : a10, t2);
                double k11 = add2(hi1 ? a13 : a11, t3);
                // round 2 (xor 2): keep one batch
                double s0 = hi2 ? k00 : k01;
                double s1 = hi2 ? k10 : k11;
                s0 = __shfl_xor_sync(0xffffffffu, s0, 2);
                s1 = __shfl_xor_sync(0xffffffffu, s1, 2);
                double f0 = add2(hi2 ? k01 : k00, s0);   // (i,f)
                double f1 = add2(hi2 ? k11 : k10, s1);   // (g,o)

                float gi, gf, gg, go;
                upk2(f0, gi, gf); upk2(f1, gg, go);
                gi = sigf(gi + bi);
                gf = sigf(gf + bf);
                gg = tanh_fast(gg + bg);
                go = sigf(go + bo);
                c = fmaf(gf, c, gi * gg);
                float h = go * tanh_fast(c);
                double hh = pk2(h, h);
                *(double*)&v1d[nxt][26 + unit][2 * beta] = hh;  // L1 next step
                *(double*)&v2d[cur][unit][2 * beta] = hh;       // L2 (skewed)
                if (xact) *(double*)&v1d[nxt][xi][2 * xb] = pk2(xr, xr);
            }
        } else {
            if (n >= 1) {
                double a00 = 0, a01 = 0, a02 = 0, a03 = 0;
                double a10 = 0, a11 = 0, a12 = 0, a13 = 0;
                const float* base = &v2d[nxt][0][0] + 8 * kq;
#pragma unroll
                for (int kk = 0; kk < 24; kk++) {
                    const float* r = base + 32 * kk;
                    double2 vA = *(const double2*)r;
                    double2 vB = *(const double2*)(r + 4);
                    fma2(a00, wp0[kk], vA.x); fma2(a01, wp0[kk], vA.y);
                    fma2(a02, wp0[kk], vB.x); fma2(a03, wp0[kk], vB.y);
                    fma2(a10, wp1[kk], vA.x); fma2(a11, wp1[kk], vA.y);
                    fma2(a12, wp1[kk], vB.x); fma2(a13, wp1[kk], vB.y);
                }
                double t0 = hi1 ? a00 : a02;
                double t1 = hi1 ? a01 : a03;
                double t2 = hi1 ? a10 : a12;
                double t3 = hi1 ? a11 : a13;
                t0 = __shfl_xor_sync(0xffffffffu, t0, 1);
                t1 = __shfl_xor_sync(0xffffffffu, t1, 1);
                t2 = __shfl_xor_sync(0xffffffffu, t2, 1);
                t3 = __shfl_xor_sync(0xffffffffu, t3, 1);
                double k00 = add2(hi1 ? a02 : a00, t0);
                double k01 = add2(hi1 ? a03 : a01, t1);
                double k10 = add2(hi1 ? a12 : a10, t2);
                double k11 = add2(hi1 ? a13 : a11, t3);
                double s0 = hi2 ? k00 : k01;
                double s1 = hi2 ? k10 : k11;
                s0 = __shfl_xor_sync(0xffffffffu, s0, 2);
                s1 = __shfl_xor_sync(0xffffffffu, s1, 2);
                double f0 = add2(hi2 ? k01 : k00, s0);
                double f1 = add2(hi2 ? k11 : k10, s1);

                float gi, gf, gg, go;
                upk2(f0, gi, gf); upk2(f1, gg, go);
                gi = sigf(gi + bi);
                gf = sigf(gf + bf);
                gg = tanh_fast(gg + bg);
                go = sigf(go + bo);
                c = fmaf(gf, c, gi * gg);
                float h = go * tanh_fast(c);
                *(double*)&v2d[cur][64 + unit][2 * beta] = pk2(h, h);
            }
        }
        __syncthreads();
    }

    // ================= MLP head =================
    // final h2 (step 999) lives in v2d[0] rows 64-95 (duplicated; read copy 0)
    if (tid < 64) {
        const int b = tid >> 4, j = tid & 15;
        float s = b_fc1[j];
#pragma unroll
        for (int k2 = 0; k2 < 32; k2++)
            s = fmaf(v2d[0][64 + k2][2 * b], w_fc1[j * 32 + k2], s);
        sf[b][j] = fmaxf(s, 0.0f);
    }
    __syncthreads();
    if (tid < 40) {
        const int b = tid / 10, o = tid % 10;
        float s = b_fc2[o];
#pragma unroll
        for (int j = 0; j < 16; j++) s = fmaf(sf[b][j], w_fc2[o * 16 + j], s);
        out[(bbase + b) * 10 + o] = s;
    }
}

extern "C" void kernel_launch(void* const* d_in, const int* in_sizes, int n_in,
                              void* d_out, int out_size)
{
    const float* x     = (const float*)d_in[0];
    const float* w_ih1 = (const float*)d_in[1];
    const float* w_hh1 = (const float*)d_in[2];
    const float* b_ih1 = (const float*)d_in[3];
    const float* b_hh1 = (const float*)d_in[4];
    const float* w_ih2 = (const float*)d_in[5];
    const float* w_hh2 = (const float*)d_in[6];
    const float* b_ih2 = (const float*)d_in[7];
    const float* b_hh2 = (const float*)d_in[8];
    const float* w_fc1 = (const float*)d_in[9];
    const float* b_fc1 = (const float*)d_in[10];
    const float* w_fc2 = (const float*)d_in[11];
    const float* b_fc2 = (const float*)d_in[12];
    float* out = (float*)d_out;

    audio_lstm_kernel<<<128, 384>>>(x, w_ih1, w_hh1, b_ih1, b_hh1,
                                    w_ih2, w_hh2, b_ih2, b_hh2,
                                    w_fc1, b_fc1, w_fc2, b_fc2, out);
}

// round 4
// speedup vs baseline: 1.2177x; 1.2177x over previous
#include <cuda_runtime.h>

// Round 4: fused 2-layer LSTM + MLP, persistent skewed-pipeline kernel.
// Grid 128 x 384. CTA owns 4 batch rows, 1000 steps.
//
// Layout: SMEM activation rows are k-PAIRS: row p (32B) = [b0:(v_{2p},v_{2p+1}),
// b1:(...), b2, b3]. One LDS.128 = 2 batches x 1 k-pair, feeds fma.rn.f32x2
// whose lanes are (even k, odd k) partials; weights pre-packed as doubles in
// registers (1 reg per k, no per-step movs).
//
// L1 (256 thr): thread = (unit u<64, sel in {if,go}, khalf). lane fold + 6
//   shfl.32 leave each thread with all 4 gates of (u, batch=2*kh+sel); LSTM
//   update is local (c in register), no staging, no role barriers.
// L2 (128 thr): same with u<32, one step behind (skewed).
// Single __syncthreads per iteration; double-buffered activation arrays.

#define T_STEPS 1000

__device__ __forceinline__ float sigf(float x) {
    float e = exp2f(-1.4426950408889634f * x);
    return __fdividef(1.0f, 1.0f + e);
}
__device__ __forceinline__ float tanh_fast(float x) {
    x = fminf(16.0f, fmaxf(-16.0f, x));
    float e = exp2f(-2.8853900817779268f * x);   // exp(-2x)
    return __fdividef(1.0f - e, 1.0f + e);
}
__device__ __forceinline__ double pk2(float lo, float hi) {
    double r; asm("mov.b64 %0, {%1,%2};" : "=d"(r) : "f"(lo), "f"(hi)); return r;
}
__device__ __forceinline__ void upk2(double v, float &lo, float &hi) {
    asm("mov.b64 {%0,%1}, %2;" : "=f"(lo), "=f"(hi) : "d"(v));
}
__device__ __forceinline__ void fma2(double &acc, double a, double b) {
    asm("fma.rn.f32x2 %0, %1, %2, %0;" : "+d"(acc) : "d"(a), "d"(b));
}
// fold f32x2 lanes to scalar sum
__device__ __forceinline__ float fold(double v) {
    float lo, hi; upk2(v, lo, hi); return lo + hi;
}

__global__ void __launch_bounds__(384, 1)
audio_lstm_kernel(const float* __restrict__ x,
                  const float* __restrict__ w_ih1, const float* __restrict__ w_hh1,
                  const float* __restrict__ b_ih1, const float* __restrict__ b_hh1,
                  const float* __restrict__ w_ih2, const float* __restrict__ w_hh2,
                  const float* __restrict__ b_ih2, const float* __restrict__ b_hh2,
                  const float* __restrict__ w_fc1, const float* __restrict__ b_fc1,
                  const float* __restrict__ w_fc2, const float* __restrict__ b_fc2,
                  float* __restrict__ out)
{
    // v1: pairs 0..12 = x (k 0..25), 13..44 = h1 (k 26..89), 45 = zero pad.
    __shared__ __align__(16) float v1[2][46][8];
    // v2: pairs 0..31 = h1 (k 0..63), 32..47 = h2 (k 64..95).
    __shared__ __align__(16) float v2[2][48][8];
    __shared__ float sf[4][16];

    const int tid = threadIdx.x;
    const int bbase = blockIdx.x * 4;
    const bool isL1 = tid < 256;

    // Role-shared registers
    double wpA[24], wpB[24];      // packed (k even, k odd) weights, 2 gates
    float bi, bf, bg, bo;
    float c = 0.0f;
    int u, sel, kh;

    if (isL1) {
        u = tid >> 2; sel = (tid >> 1) & 1; kh = tid & 1;
        const int gA = sel ? (128 + u) : u;          // g : i
        const int gB = sel ? (192 + u) : (64 + u);   // o : f
#pragma unroll
        for (int kk = 0; kk < 24; kk++) {
            float a0 = 0.f, a1 = 0.f, q0 = 0.f, q1 = 0.f;
            if (kk < 23) {
                int p = kh * 23 + kk;
                int k0 = 2 * p, k1 = 2 * p + 1;
                a0 = (k0 < 26) ? w_ih1[gA * 26 + k0] : (k0 < 90 ? w_hh1[gA * 64 + k0 - 26] : 0.f);
                a1 = (k1 < 26) ? w_ih1[gA * 26 + k1] : (k1 < 90 ? w_hh1[gA * 64 + k1 - 26] : 0.f);
                q0 = (k0 < 26) ? w_ih1[gB * 26 + k0] : (k0 < 90 ? w_hh1[gB * 64 + k0 - 26] : 0.f);
                q1 = (k1 < 26) ? w_ih1[gB * 26 + k1] : (k1 < 90 ? w_hh1[gB * 64 + k1 - 26] : 0.f);
            }
            wpA[kk] = pk2(a0, a1);
            wpB[kk] = pk2(q0, q1);
        }
        bi = b_ih1[u] + b_hh1[u];
        bf = b_ih1[64 + u] + b_hh1[64 + u];
        bg = b_ih1[128 + u] + b_hh1[128 + u];
        bo = b_ih1[192 + u] + b_hh1[192 + u];
    } else {
        const int t2 = tid - 256;
        u = t2 >> 2; sel = (t2 >> 1) & 1; kh = t2 & 1;
        const int gA = sel ? (64 + u) : u;
        const int gB = sel ? (96 + u) : (32 + u);
#pragma unroll
        for (int kk = 0; kk < 24; kk++) {
            int p = kh * 24 + kk;
            int k0 = 2 * p, k1 = 2 * p + 1;
            float a0 = (k0 < 64) ? w_ih2[gA * 64 + k0] : w_hh2[gA * 32 + k0 - 64];
            float a1 = (k1 < 64) ? w_ih2[gA * 64 + k1] : w_hh2[gA * 32 + k1 - 64];
            float q0 = (k0 < 64) ? w_ih2[gB * 64 + k0] : w_hh2[gB * 32 + k0 - 64];
            float q1 = (k1 < 64) ? w_ih2[gB * 64 + k1] : w_hh2[gB * 32 + k1 - 64];
            wpA[kk] = pk2(a0, a1);
            wpB[kk] = pk2(q0, q1);
        }
        bi = b_ih2[u] + b_hh2[u];
        bf = b_ih2[32 + u] + b_hh2[32 + u];
        bg = b_ih2[64 + u] + b_hh2[64 + u];
        bo = b_ih2[96 + u] + b_hh2[96 + u];
    }

    // h-output location for this thread's unit
    const int hrow1 = 13 + (u >> 1);        // L1: v1 pair row
    const int hrow2 = u >> 1;               // L1 -> v2 rows 0..31 ; L2 -> +32
    const int hlane = u & 1;
    const int myb = 2 * kh + sel;           // batch this thread owns post-shuffle

    // Zero both buffers
    for (int idx = tid; idx < 2 * 46 * 8; idx += 384) ((float*)v1)[idx] = 0.0f;
    for (int idx = tid; idx < 2 * 48 * 8; idx += 384) ((float*)v2)[idx] = 0.0f;

    // x layout: x[b][i][t]
    const int xi = tid % 26;
    const int xb = tid / 26;
    const float* xptr = x + (size_t)(bbase + xb) * 26 * T_STEPS + (size_t)xi * T_STEPS;
    __syncthreads();
    if (tid < 104) v1[0][xi >> 1][xb * 2 + (xi & 1)] = xptr[0];
    __syncthreads();

    // iter n: L1 step n (reads v1[cur], writes v1[nxt] + v2[cur] rows 0..31);
    //         L2 step n-1 (reads v2[nxt], writes v2[cur] rows 32..47).
    for (int n = 0; n <= T_STEPS; n++) {
        const int cur = n & 1, nxt = cur ^ 1;
        float pA0, pA1, pA2, pA3, pB0, pB1, pB2, pB3;
        bool active;

        if (isL1) {
            active = (n < T_STEPS);
            if (active) {
                double aA0 = 0, aA1 = 0, aA2 = 0, aA3 = 0;
                double aB0 = 0, aB1 = 0, aB2 = 0, aB3 = 0;
                const float* base = &v1[cur][kh * 23][0];
#pragma unroll
                for (int kk = 0; kk < 23; kk++) {
                    const float* r = base + 8 * kk;
                    double2 vlo = *(const double2*)r;        // batches 0,1
                    double2 vhi = *(const double2*)(r + 4);  // batches 2,3
                    fma2(aA0, wpA[kk], vlo.x); fma2(aA1, wpA[kk], vlo.y);
                    fma2(aA2, wpA[kk], vhi.x); fma2(aA3, wpA[kk], vhi.y);
                    fma2(aB0, wpB[kk], vlo.x); fma2(aB1, wpB[kk], vlo.y);
                    fma2(aB2, wpB[kk], vhi.x); fma2(aB3, wpB[kk], vhi.y);
                }
                pA0 = fold(aA0); pA1 = fold(aA1); pA2 = fold(aA2); pA3 = fold(aA3);
                pB0 = fold(aB0); pB1 = fold(aB1); pB2 = fold(aB2); pB3 = fold(aB3);
            }
        } else {
            active = (n >= 1);
            if (active) {
                double aA0 = 0, aA1 = 0, aA2 = 0, aA3 = 0;
                double aB0 = 0, aB1 = 0, aB2 = 0, aB3 = 0;
                const float* base = &v2[nxt][kh * 24][0];
#pragma unroll
                for (int kk = 0; kk < 24; kk++) {
                    const float* r = base + 8 * kk;
                    double2 vlo = *(const double2*)r;
                    double2 vhi = *(const double2*)(r + 4);
                    fma2(aA0, wpA[kk], vlo.x); fma2(aA1, wpA[kk], vlo.y);
                    fma2(aA2, wpA[kk], vhi.x); fma2(aA3, wpA[kk], vhi.y);
                    fma2(aB0, wpB[kk], vlo.x); fma2(aB1, wpB[kk], vlo.y);
                    fma2(aB2, wpB[kk], vhi.x); fma2(aB3, wpB[kk], vhi.y);
                }
                pA0 = fold(aA0); pA1 = fold(aA1); pA2 = fold(aA2); pA3 = fold(aA3);
                pB0 = fold(aB0); pB1 = fold(aB1); pB2 = fold(aB2); pB3 = fold(aB3);
            }
        }

        if (active) {
            // Round A (xor 1, cross k-half): kh=0 keeps batches {0,1}, kh=1 {2,3}
            float sA0 = kh ? pA0 : pA2;
            float sA1 = kh ? pA1 : pA3;
            float sB0 = kh ? pB0 : pB2;
            float sB1 = kh ? pB1 : pB3;
            sA0 = __shfl_xor_sync(0xffffffffu, sA0, 1);
            sA1 = __shfl_xor_sync(0xffffffffu, sA1, 1);
            sB0 = __shfl_xor_sync(0xffffffffu, sB0, 1);
            sB1 = __shfl_xor_sync(0xffffffffu, sB1, 1);
            float mA0 = (kh ? pA2 : pA0) + sA0;   // gate A, batch 2*kh+0
            float mA1 = (kh ? pA3 : pA1) + sA1;   // gate A, batch 2*kh+1
            float mB0 = (kh ? pB2 : pB0) + sB0;
            float mB1 = (kh ? pB3 : pB1) + sB1;

            // Round B (xor 2, cross gate-sel): keep batch 2*kh+sel, trade gates
            float sendA = sel ? mA0 : mA1;
            float sendB = sel ? mB0 : mB1;
            float rA = __shfl_xor_sync(0xffffffffu, sendA, 2);
            float rB = __shfl_xor_sync(0xffffffffu, sendB, 2);
            float ownA = sel ? mA1 : mA0;
            float ownB = sel ? mB1 : mB0;
            // sel=0 owns (i,f), partner gives (g,o); sel=1 owns (g,o)
            float gi = (sel ? rA : ownA) + bi;
            float gf = (sel ? rB : ownB) + bf;
            float gg = (sel ? ownA : rA) + bg;
            float go = (sel ? ownB : rB) + bo;

            gi = sigf(gi);
            gf = sigf(gf);
            gg = tanh_fast(gg);
            go = sigf(go);
            c = fmaf(gf, c, gi * gg);
            float h = go * tanh_fast(c);

            if (isL1) {
                v1[nxt][hrow1][myb * 2 + hlane] = h;
                v2[cur][hrow2][myb * 2 + hlane] = h;
                // x prefetch/store for next step
                if (tid < 104 && n + 1 < T_STEPS)
                    v1[nxt][xi >> 1][xb * 2 + (xi & 1)] = xptr[n + 1];
            } else {
                v2[cur][32 + hrow2][myb * 2 + hlane] = h;
            }
        }
        __syncthreads();
    }

    // ================= MLP head =================
    // final h2 (step 999) is in v2[0] pairs 32..47
    if (tid < 64) {
        const int b = tid >> 4, j = tid & 15;
        float s = b_fc1[j];
#pragma unroll
        for (int k2 = 0; k2 < 32; k2++)
            s = fmaf(v2[0][32 + (k2 >> 1)][b * 2 + (k2 & 1)], w_fc1[j * 32 + k2], s);
        sf[b][j] = fmaxf(s, 0.0f);
    }
    __syncthreads();
    if (tid < 40) {
        const int b = tid / 10, o = tid % 10;
        float s = b_fc2[o];
#pragma unroll
        for (int j = 0; j < 16; j++) s = fmaf(sf[b][j], w_fc2[o * 16 + j], s);
        out[(bbase + b) * 10 + o] = s;
    }
}

extern "C" void kernel_launch(void* const* d_in, const int* in_sizes, int n_in,
                              void* d_out, int out_size)
{
    const float* x     = (const float*)d_in[0];
    const float* w_ih1 = (const float*)d_in[1];
    const float* w_hh1 = (const float*)d_in[2];
    const float* b_ih1 = (const float*)d_in[3];
    const float* b_hh1 = (const float*)d_in[4];
    const float* w_ih2 = (const float*)d_in[5];
    const float* w_hh2 = (const float*)d_in[6];
    const float* b_ih2 = (const float*)d_in[7];
    const float* b_hh2 = (const float*)d_in[8];
    const float* w_fc1 = (const float*)d_in[9];
    const float* b_fc1 = (const float*)d_in[10];
    const float* w_fc2 = (const float*)d_in[11];
    const float* b_fc2 = (const float*)d_in[12];
    float* out = (float*)d_out;

    audio_lstm_kernel<<<128, 384>>>(x, w_ih1, w_hh1, b_ih1, b_hh1,
                                    w_ih2, w_hh2, b_ih2, b_hh2,
                                    w_fc1, b_fc1, w_fc2, b_fc2, out);
}

// round 5
// speedup vs baseline: 1.3733x; 1.1278x over previous
#include <cuda_runtime.h>

// Round 5: fused 2-layer LSTM + MLP, persistent skewed-pipeline kernel.
// R4 skeleton (thread = (unit, gate-sel, k-half); butterfly shfl; local LSTM
// update; single __syncthreads/step) plus:
//  - L1 x-projection split out and PRECOMPUTED during the previous
//    iteration's tail (fills shfl/MUFU latency shadows with fma work),
//    accumulators carried across the barrier in registers.
//  - x staged two steps ahead in a dedicated double-buffered xbuf.
//  - 2x unrolled main loop -> compile-time buffer indices.

#define T_STEPS 1000

__device__ __forceinline__ float sigf(float x) {
    float e = exp2f(-1.4426950408889634f * x);
    return __fdividef(1.0f, 1.0f + e);
}
__device__ __forceinline__ float tanh_fast(float x) {
    x = fminf(16.0f, fmaxf(-16.0f, x));
    float e = exp2f(-2.8853900817779268f * x);   // exp(-2x)
    return __fdividef(1.0f - e, 1.0f + e);
}
__device__ __forceinline__ double pk2(float lo, float hi) {
    double r; asm("mov.b64 %0, {%1,%2};" : "=d"(r) : "f"(lo), "f"(hi)); return r;
}
__device__ __forceinline__ void upk2(double v, float &lo, float &hi) {
    asm("mov.b64 {%0,%1}, %2;" : "=f"(lo), "=f"(hi) : "d"(v));
}
__device__ __forceinline__ void fma2(double &acc, double a, double b) {
    asm("fma.rn.f32x2 %0, %1, %2, %0;" : "+d"(acc) : "d"(a), "d"(b));
}
__device__ __forceinline__ float fold(double v) {
    float lo, hi; upk2(v, lo, hi); return lo + hi;
}

__global__ void __launch_bounds__(384, 1)
audio_lstm_kernel(const float* __restrict__ x,
                  const float* __restrict__ w_ih1, const float* __restrict__ w_hh1,
                  const float* __restrict__ b_ih1, const float* __restrict__ b_hh1,
                  const float* __restrict__ w_ih2, const float* __restrict__ w_hh2,
                  const float* __restrict__ b_ih2, const float* __restrict__ b_hh2,
                  const float* __restrict__ w_fc1, const float* __restrict__ b_fc1,
                  const float* __restrict__ w_fc2, const float* __restrict__ b_fc2,
                  float* __restrict__ out)
{
    // h1 pair rows (k-pairs 0..31 of the 64 h1 values), double buffered
    __shared__ __align__(16) float v1h[2][32][8];
    // x pair rows 0..12 (k 0..25) + pad row 13 (zero), double buffered
    __shared__ __align__(16) float xbuf[2][14][8];
    // v2: pairs 0..31 = h1 (k 0..63), 32..47 = h2 (k 64..95), double buffered
    __shared__ __align__(16) float v2[2][48][8];
    __shared__ float sf[4][16];

    const int tid = threadIdx.x;
    const int bbase = blockIdx.x * 4;
    const bool isL1 = tid < 256;

    // Role-shared registers
    double whA[16], whB[16];     // L1: h-part weights / L2: all 24 pairs (uses wx too)
    double wxA[8], wxB[8];       // L1: x-part weights (<=7 used)
    float bi, bf, bg, bo;
    float c = 0.0f;
    int u, sel, kh;

    if (isL1) {
        u = tid >> 2; sel = (tid >> 1) & 1; kh = tid & 1;
        const int gA = sel ? (128 + u) : u;          // g : i
        const int gB = sel ? (192 + u) : (64 + u);   // o : f
#pragma unroll
        for (int j = 0; j < 7; j++) {                // x pairs: p = 2j+kh < 13
            int p = 2 * j + kh;
            float a0 = 0.f, a1 = 0.f, q0 = 0.f, q1 = 0.f;
            if (p < 13) {
                int k0 = 2 * p, k1 = 2 * p + 1;
                a0 = w_ih1[gA * 26 + k0]; a1 = w_ih1[gA * 26 + k1];
                q0 = w_ih1[gB * 26 + k0]; q1 = w_ih1[gB * 26 + k1];
            }
            wxA[j] = pk2(a0, a1); wxB[j] = pk2(q0, q1);
        }
        wxA[7] = 0.0; wxB[7] = 0.0;
#pragma unroll
        for (int j = 0; j < 16; j++) {               // h pairs: p = 2j+kh < 32
            int p = 2 * j + kh;
            int k0 = 2 * p, k1 = 2 * p + 1;          // h index 0..63
            whA[j] = pk2(w_hh1[gA * 64 + k0], w_hh1[gA * 64 + k1]);
            whB[j] = pk2(w_hh1[gB * 64 + k0], w_hh1[gB * 64 + k1]);
        }
        bi = b_ih1[u] + b_hh1[u];
        bf = b_ih1[64 + u] + b_hh1[64 + u];
        bg = b_ih1[128 + u] + b_hh1[128 + u];
        bo = b_ih1[192 + u] + b_hh1[192 + u];
    } else {
        const int t2 = tid - 256;
        u = t2 >> 2; sel = (t2 >> 1) & 1; kh = t2 & 1;
        const int gA = sel ? (64 + u) : u;
        const int gB = sel ? (96 + u) : (32 + u);
        // 24 contiguous pairs per k-half: whA/whB hold first 16, wxA/wxB last 8
#pragma unroll
        for (int kk = 0; kk < 24; kk++) {
            int p = kh * 24 + kk;
            int k0 = 2 * p, k1 = 2 * p + 1;
            float a0 = (k0 < 64) ? w_ih2[gA * 64 + k0] : w_hh2[gA * 32 + k0 - 64];
            float a1 = (k1 < 64) ? w_ih2[gA * 64 + k1] : w_hh2[gA * 32 + k1 - 64];
            float q0 = (k0 < 64) ? w_ih2[gB * 64 + k0] : w_hh2[gB * 32 + k0 - 64];
            float q1 = (k1 < 64) ? w_ih2[gB * 64 + k1] : w_hh2[gB * 32 + k1 - 64];
            if (kk < 16) { whA[kk] = pk2(a0, a1); whB[kk] = pk2(q0, q1); }
            else         { wxA[kk - 16] = pk2(a0, a1); wxB[kk - 16] = pk2(q0, q1); }
        }
        bi = b_ih2[u] + b_hh2[u];
        bf = b_ih2[32 + u] + b_hh2[32 + u];
        bg = b_ih2[64 + u] + b_hh2[64 + u];
        bo = b_ih2[96 + u] + b_hh2[96 + u];
    }

    const int hrow = u >> 1;
    const int hlane = u & 1;
    const int myb = 2 * kh + sel;

    // Zero buffers
    for (int idx = tid; idx < 2 * 32 * 8; idx += 384) ((float*)v1h)[idx] = 0.0f;
    for (int idx = tid; idx < 2 * 14 * 8; idx += 384) ((float*)xbuf)[idx] = 0.0f;
    for (int idx = tid; idx < 2 * 48 * 8; idx += 384) ((float*)v2)[idx] = 0.0f;

    // x layout: x[b][i][t]
    const int xi = tid % 26;
    const int xb = tid / 26;
    const bool isldr = tid < 104;
    const int xrow = xi >> 1, xcol = xb * 2 + (xi & 1);
    const float* xptr = x + (size_t)(bbase + xb) * 26 * T_STEPS + (size_t)xi * T_STEPS;
    __syncthreads();
    if (isldr) {
        xbuf[0][xrow][xcol] = xptr[0];
        xbuf[1][xrow][xcol] = xptr[1];
    }
    __syncthreads();

    // carried x-part accumulators (valid for the step the next body processes)
    double xA0 = 0, xA1 = 0, xA2 = 0, xA3 = 0, xB0 = 0, xB1 = 0, xB2 = 0, xB3 = 0;
    if (isL1) {   // precompute x-part for step 0 from xbuf[0]
#pragma unroll
        for (int j = 0; j < 7; j++) {
            const float* r = &xbuf[0][2 * j + kh][0];   // row 13 pad when kh=1,j=6
            double2 vlo = *(const double2*)r;
            double2 vhi = *(const double2*)(r + 4);
            fma2(xA0, wxA[j], vlo.x); fma2(xA1, wxA[j], vlo.y);
            fma2(xA2, wxA[j], vhi.x); fma2(xA3, wxA[j], vhi.y);
            fma2(xB0, wxB[j], vlo.x); fma2(xB1, wxB[j], vlo.y);
            fma2(xB2, wxB[j], vhi.x); fma2(xB3, wxB[j], vhi.y);
        }
    }

    // iter n: L1 step n (reads v1h[cur]+carried xacc, writes v1h[nxt], v2[cur],
    //         xbuf[cur] (x for n+2), precomputes xacc for n+1 from xbuf[nxt]);
    //         L2 step n-1 (reads v2[nxt], writes v2[cur] rows 32..47).
#define BODY(n, cur, nxt)                                                          \
    {                                                                              \
        if (isL1) {                                                                \
            if ((n) < T_STEPS) {                                                   \
                float xr = 0.0f;                                                   \
                const bool ldr = isldr && ((n) + 2 < T_STEPS);                     \
                if (ldr) xr = xptr[(n) + 2];                                       \
                double aA0 = xA0, aA1 = xA1, aA2 = xA2, aA3 = xA3;                 \
                double aB0 = xB0, aB1 = xB1, aB2 = xB2, aB3 = xB3;                 \
                _Pragma("unroll")                                                  \
                for (int j = 0; j < 16; j++) {                                     \
                    const float* r = &v1h[cur][2 * j + kh][0];                     \
                    double2 vlo = *(const double2*)r;                              \
                    double2 vhi = *(const double2*)(r + 4);                        \
                    fma2(aA0, whA[j], vlo.x); fma2(aA1, whA[j], vlo.y);            \
                    fma2(aA2, whA[j], vhi.x); fma2(aA3, whA[j], vhi.y);            \
                    fma2(aB0, whB[j], vlo.x); fma2(aB1, whB[j], vlo.y);            \
                    fma2(aB2, whB[j], vhi.x); fma2(aB3, whB[j], vhi.y);            \
                }                                                                  \
                float pA0 = fold(aA0), pA1 = fold(aA1), pA2 = fold(aA2), pA3 = fold(aA3); \
                float pB0 = fold(aB0), pB1 = fold(aB1), pB2 = fold(aB2), pB3 = fold(aB3); \
                float sA0 = kh ? pA0 : pA2, sA1 = kh ? pA1 : pA3;                  \
                float sB0 = kh ? pB0 : pB2, sB1 = kh ? pB1 : pB3;                  \
                sA0 = __shfl_xor_sync(0xffffffffu, sA0, 1);                        \
                sA1 = __shfl_xor_sync(0xffffffffu, sA1, 1);                        \
                sB0 = __shfl_xor_sync(0xffffffffu, sB0, 1);                        \
                sB1 = __shfl_xor_sync(0xffffffffu, sB1, 1);                        \
                float mA0 = (kh ? pA2 : pA0) + sA0;                                \
                float mA1 = (kh ? pA3 : pA1) + sA1;                                \
                float mB0 = (kh ? pB2 : pB0) + sB0;                                \
                float mB1 = (kh ? pB3 : pB1) + sB1;                                \
                float rA = __shfl_xor_sync(0xffffffffu, sel ? mA0 : mA1, 2);       \
                float rB = __shfl_xor_sync(0xffffffffu, sel ? mB0 : mB1, 2);       \
                float ownA = sel ? mA1 : mA0, ownB = sel ? mB1 : mB0;              \
                float gi = (sel ? rA : ownA) + bi;                                 \
                float gf = (sel ? rB : ownB) + bf;                                 \
                float gg = (sel ? ownA : rA) + bg;                                 \
                float go = (sel ? ownB : rB) + bo;                                 \
                gi = sigf(gi); gf = sigf(gf); gg = tanh_fast(gg); go = sigf(go);   \
                c = fmaf(gf, c, gi * gg);                                          \
                float h = go * tanh_fast(c);                                       \
                v1h[nxt][hrow][myb * 2 + hlane] = h;                               \
                v2[cur][hrow][myb * 2 + hlane] = h;                                \
                if (ldr) xbuf[cur][xrow][xcol] = xr;                               \
                if ((n) + 1 < T_STEPS) {                                           \
                    xA0 = 0; xA1 = 0; xA2 = 0; xA3 = 0;                            \
                    xB0 = 0; xB1 = 0; xB2 = 0; xB3 = 0;                            \
                    _Pragma("unroll")                                              \
                    for (int j = 0; j < 7; j++) {                                  \
                        const float* r = &xbuf[nxt][2 * j + kh][0];                \
                        double2 vlo = *(const double2*)r;                          \
                        double2 vhi = *(const double2*)(r + 4);                    \
                        fma2(xA0, wxA[j], vlo.x); fma2(xA1, wxA[j], vlo.y);        \
                        fma2(xA2, wxA[j], vhi.x); fma2(xA3, wxA[j], vhi.y);        \
                        fma2(xB0, wxB[j], vlo.x); fma2(xB1, wxB[j], vlo.y);        \
                        fma2(xB2, wxB[j], vhi.x); fma2(xB3, wxB[j], vhi.y);        \
                    }                                                              \
                }                                                                  \
            }                                                                      \
        } else {                                                                   \
            if ((n) >= 1) {                                                        \
                double aA0 = 0, aA1 = 0, aA2 = 0, aA3 = 0;                         \
                double aB0 = 0, aB1 = 0, aB2 = 0, aB3 = 0;                         \
                const float* base = &v2[nxt][kh * 24][0];                          \
                _Pragma("unroll")                                                  \
                for (int kk = 0; kk < 24; kk++) {                                  \
                    const float* r = base + 8 * kk;                                \
                    double2 vlo = *(const double2*)r;                              \
                    double2 vhi = *(const double2*)(r + 4);                        \
                    double wa = (kk < 16) ? whA[kk] : wxA[kk - 16];                \
                    double wb = (kk < 16) ? whB[kk] : wxB[kk - 16];                \
                    fma2(aA0, wa, vlo.x); fma2(aA1, wa, vlo.y);                    \
                    fma2(aA2, wa, vhi.x); fma2(aA3, wa, vhi.y);                    \
                    fma2(aB0, wb, vlo.x); fma2(aB1, wb, vlo.y);                    \
                    fma2(aB2, wb, vhi.x); fma2(aB3, wb, vhi.y);                    \
                }                                                                  \
                float pA0 = fold(aA0), pA1 = fold(aA1), pA2 = fold(aA2), pA3 = fold(aA3); \
                float pB0 = fold(aB0), pB1 = fold(aB1), pB2 = fold(aB2), pB3 = fold(aB3); \
                float sA0 = kh ? pA0 : pA2, sA1 = kh ? pA1 : pA3;                  \
                float sB0 = kh ? pB0 : pB2, sB1 = kh ? pB1 : pB3;                  \
                sA0 = __shfl_xor_sync(0xffffffffu, sA0, 1);                        \
                sA1 = __shfl_xor_sync(0xffffffffu, sA1, 1);                        \
                sB0 = __shfl_xor_sync(0xffffffffu, sB0, 1);                        \
                sB1 = __shfl_xor_sync(0xffffffffu, sB1, 1);                        \
                float mA0 = (kh ? pA2 : pA0) + sA0;                                \
                float mA1 = (kh ? pA3 : pA1) + sA1;                                \
                float mB0 = (kh ? pB2 : pB0) + sB0;                                \
                float mB1 = (kh ? pB3 : pB1) + sB1;                                \
                float rA = __shfl_xor_sync(0xffffffffu, sel ? mA0 : mA1, 2);       \
                float rB = __shfl_xor_sync(0xffffffffu, sel ? mB0 : mB1, 2);       \
                float ownA = sel ? mA1 : mA0, ownB = sel ? mB1 : mB0;              \
                float gi = (sel ? rA : ownA) + bi;                                 \
                float gf = (sel ? rB : ownB) + bf;                                 \
                float gg = (sel ? ownA : rA) + bg;                                 \
                float go = (sel ? ownB : rB) + bo;                                 \
                gi = sigf(gi); gf = sigf(gf); gg = tanh_fast(gg); go = sigf(go);   \
                c = fmaf(gf, c, gi * gg);                                          \
                float h = go * tanh_fast(c);                                       \
                v2[cur][32 + hrow][myb * 2 + hlane] = h;                           \
            }                                                                      \
        }                                                                          \
        __syncthreads();                                                           \
    }

    for (int n = 0; n < T_STEPS; n += 2) {
        BODY(n, 0, 1);
        BODY(n + 1, 1, 0);
    }
    BODY(T_STEPS, 0, 1);   // final L2-only iteration (step 999)
#undef BODY

    // ================= MLP head =================
    // final h2 (step 999) is in v2[0] pairs 32..47
    if (tid < 64) {
        const int b = tid >> 4, j = tid & 15;
        float s = b_fc1[j];
#pragma unroll
        for (int k2 = 0; k2 < 32; k2++)
            s = fmaf(v2[0][32 + (k2 >> 1)][b * 2 + (k2 & 1)], w_fc1[j * 32 + k2], s);
        sf[b][j] = fmaxf(s, 0.0f);
    }
    __syncthreads();
    if (tid < 40) {
        const int b = tid / 10, o = tid % 10;
        float s = b_fc2[o];
#pragma unroll
        for (int j = 0; j < 16; j++) s = fmaf(sf[b][j], w_fc2[o * 16 + j], s);
        out[(bbase + b) * 10 + o] = s;
    }
}

extern "C" void kernel_launch(void* const* d_in, const int* in_sizes, int n_in,
                              void* d_out, int out_size)
{
    const float* x     = (const float*)d_in[0];
    const float* w_ih1 = (const float*)d_in[1];
    const float* w_hh1 = (const float*)d_in[2];
    const float* b_ih1 = (const float*)d_in[3];
    const float* b_hh1 = (const float*)d_in[4];
    const float* w_ih2 = (const float*)d_in[5];
    const float* w_hh2 = (const float*)d_in[6];
    const float* b_ih2 = (const float*)d_in[7];
    const float* b_hh2 = (const float*)d_in[8];
    const float* w_fc1 = (const float*)d_in[9];
    const float* b_fc1 = (const float*)d_in[10];
    const float* w_fc2 = (const float*)d_in[11];
    const float* b_fc2 = (const float*)d_in[12];
    float* out = (float*)d_out;

    audio_lstm_kernel<<<128, 384>>>(x, w_ih1, w_hh1, b_ih1, b_hh1,
                                    w_ih2, w_hh2, b_ih2, b_hh2,
                                    w_fc1, b_fc1, w_fc2, b_fc2, out);
}